// round 1
// baseline (speedup 1.0000x reference)
#include <cuda_runtime.h>
#include <cuda_bf16.h>
#include <cstdint>

// Problem constants: x [B=4, K=8192, D=1024], W [D,D], b [D]
#define BATCH 4
#define SEQ   8192
#define DIM   1024
#define M_TOT (BATCH * SEQ)   // 32768

// Scratch: interleaved {lam, u} per element, written by GEMM epilogue, read by scan.
__device__ float2 g_scratch[(size_t)M_TOT * DIM];

// ---------------------------------------------------------------------------
// GEMM + sigmoid gate epilogue (TF32 mma.sync)
//   z[m,n] = sum_d x[m,d] * W[n,d] + b[n]
//   lam = sigmoid(z); u = (1-lam)*x[m,n]; scratch[m,n] = {lam, u}
// Tile: BM=128, BN=128, BK=16, 256 threads (8 warps, 2x4), warp tile 64x32.
// ---------------------------------------------------------------------------
#define BM 128
#define BN 128
#define BK 16
#define PADK 20   // row pad: conflict-free frag LDS + 16B-aligned cp.async chunks
#define NKT (DIM / BK)   // 64

__device__ __forceinline__ uint32_t f2tf32(float f) {
    uint32_t r;
    asm volatile("cvt.rna.tf32.f32 %0, %1;" : "=r"(r) : "f"(f));
    return r;
}

__device__ __forceinline__ void cp_async16(uint32_t saddr, const void* gptr) {
    asm volatile("cp.async.cg.shared.global [%0], [%1], 16;" :: "r"(saddr), "l"(gptr));
}
__device__ __forceinline__ void cp_commit() {
    asm volatile("cp.async.commit_group;");
}
template <int N>
__device__ __forceinline__ void cp_wait() {
    asm volatile("cp.async.wait_group %0;" :: "n"(N));
}

__device__ __forceinline__ void mma_tf32(float& c0, float& c1, float& c2, float& c3,
                                         uint32_t a0, uint32_t a1, uint32_t a2, uint32_t a3,
                                         uint32_t b0, uint32_t b1) {
    asm volatile(
        "mma.sync.aligned.m16n8k8.row.col.f32.tf32.tf32.f32 "
        "{%0,%1,%2,%3},{%4,%5,%6,%7},{%8,%9},{%0,%1,%2,%3};"
        : "+f"(c0), "+f"(c1), "+f"(c2), "+f"(c3)
        : "r"(a0), "r"(a1), "r"(a2), "r"(a3), "r"(b0), "r"(b1));
}

__global__ __launch_bounds__(256, 1)
void gemm_gate_kernel(const float* __restrict__ X, const float* __restrict__ W,
                      const float* __restrict__ bias) {
    __shared__ __align__(16) float As[2][BM][PADK];
    __shared__ __align__(16) float Bs[2][BN][PADK];

    const int tid  = threadIdx.x;
    const int lane = tid & 31;
    const int wid  = tid >> 5;
    const int wm   = wid >> 2;   // 0..1  (M direction, 64 rows each)
    const int wn   = wid & 3;    // 0..3  (N direction, 32 cols each)
    const int m0   = blockIdx.y * BM;
    const int n0   = blockIdx.x * BN;

    // copy-index mapping: 512 16B-chunks per tile, 2 per thread
    const int r1 = tid >> 2,        s1 = tid & 3;          // chunk tid
    const int r2 = (tid + 256) >> 2, s2 = (tid + 256) & 3; // chunk tid+256

    auto prefetch = [&](int kt, int st) {
        const int k0 = kt * BK;
        cp_async16((uint32_t)__cvta_generic_to_shared(&As[st][r1][s1 * 4]),
                   X + (size_t)(m0 + r1) * DIM + k0 + s1 * 4);
        cp_async16((uint32_t)__cvta_generic_to_shared(&As[st][r2][s2 * 4]),
                   X + (size_t)(m0 + r2) * DIM + k0 + s2 * 4);
        cp_async16((uint32_t)__cvta_generic_to_shared(&Bs[st][r1][s1 * 4]),
                   W + (size_t)(n0 + r1) * DIM + k0 + s1 * 4);
        cp_async16((uint32_t)__cvta_generic_to_shared(&Bs[st][r2][s2 * 4]),
                   W + (size_t)(n0 + r2) * DIM + k0 + s2 * 4);
    };

    float c[4][4][4];
    #pragma unroll
    for (int mi = 0; mi < 4; mi++)
        #pragma unroll
        for (int ni = 0; ni < 4; ni++)
            #pragma unroll
            for (int i = 0; i < 4; i++) c[mi][ni][i] = 0.0f;

    prefetch(0, 0);
    cp_commit();

    const int lq = lane >> 2;  // 0..7
    const int lr = lane & 3;   // 0..3

    for (int kt = 0; kt < NKT; kt++) {
        if (kt + 1 < NKT) prefetch(kt + 1, (kt + 1) & 1);
        cp_commit();
        cp_wait<1>();
        __syncthreads();

        const int st = kt & 1;
        #pragma unroll
        for (int ks = 0; ks < 2; ks++) {
            const int kk = ks * 8;
            uint32_t a[4][4], bf[4][2];
            #pragma unroll
            for (int mi = 0; mi < 4; mi++) {
                const int r = wm * 64 + mi * 16 + lq;
                a[mi][0] = f2tf32(As[st][r][kk + lr]);
                a[mi][1] = f2tf32(As[st][r + 8][kk + lr]);
                a[mi][2] = f2tf32(As[st][r][kk + lr + 4]);
                a[mi][3] = f2tf32(As[st][r + 8][kk + lr + 4]);
            }
            #pragma unroll
            for (int ni = 0; ni < 4; ni++) {
                const int cc = wn * 32 + ni * 8 + lq;
                bf[ni][0] = f2tf32(Bs[st][cc][kk + lr]);
                bf[ni][1] = f2tf32(Bs[st][cc][kk + lr + 4]);
            }
            #pragma unroll
            for (int mi = 0; mi < 4; mi++)
                #pragma unroll
                for (int ni = 0; ni < 4; ni++)
                    mma_tf32(c[mi][ni][0], c[mi][ni][1], c[mi][ni][2], c[mi][ni][3],
                             a[mi][0], a[mi][1], a[mi][2], a[mi][3],
                             bf[ni][0], bf[ni][1]);
        }
        __syncthreads();
    }

    // Epilogue: z -> lam -> {lam, (1-lam)*x}, 16B stores (two adjacent cols)
    #pragma unroll
    for (int ni = 0; ni < 4; ni++) {
        const int cb = n0 + wn * 32 + ni * 8 + 2 * lr;
        const float b0 = __ldg(&bias[cb]);
        const float b1 = __ldg(&bias[cb + 1]);
        #pragma unroll
        for (int mi = 0; mi < 4; mi++) {
            const int rb = m0 + wm * 64 + mi * 16 + lq;
            #pragma unroll
            for (int h = 0; h < 2; h++) {
                const int row = rb + h * 8;
                const float z0 = c[mi][ni][h * 2 + 0] + b0;
                const float z1 = c[mi][ni][h * 2 + 1] + b1;
                const float lam0 = 1.0f / (1.0f + __expf(-z0));
                const float lam1 = 1.0f / (1.0f + __expf(-z1));
                const float2 xv = *reinterpret_cast<const float2*>(
                    X + (size_t)row * DIM + cb);
                float4 outv;
                outv.x = lam0;
                outv.y = (1.0f - lam0) * xv.x;
                outv.z = lam1;
                outv.w = (1.0f - lam1) * xv.y;
                *reinterpret_cast<float4*>(&g_scratch[(size_t)row * DIM + cb]) = outv;
            }
        }
    }
}

// ---------------------------------------------------------------------------
// Sequential scan: s_k = lam_k * s_{k-1} + u_k, one thread per (b,d) chain.
// Double-buffered U=16 prefetch to keep ~32 LDG.64 in flight per warp.
// ---------------------------------------------------------------------------
#define SCAN_U 16

__global__ __launch_bounds__(32, 1)
void scan_kernel(float* __restrict__ out) {
    const int d = blockIdx.x * 32 + threadIdx.x;        // 0..1023
    const size_t base = (size_t)blockIdx.y * SEQ * DIM + d;
    const float2* __restrict__ p = g_scratch + base;
    float* __restrict__ o = out + base;

    float2 buf[2][SCAN_U];
    #pragma unroll
    for (int i = 0; i < SCAN_U; i++) buf[0][i] = __ldg(&p[(size_t)i * DIM]);

    float s = 0.0f;
    int cur = 0;
    for (int k = 0; k < SEQ; k += SCAN_U) {
        const int nk = k + SCAN_U;
        if (nk < SEQ) {
            #pragma unroll
            for (int i = 0; i < SCAN_U; i++)
                buf[cur ^ 1][i] = __ldg(&p[(size_t)(nk + i) * DIM]);
        }
        #pragma unroll
        for (int i = 0; i < SCAN_U; i++) {
            s = fmaf(buf[cur][i].x, s, buf[cur][i].y);
            o[(size_t)(k + i) * DIM] = s;
        }
        cur ^= 1;
    }
}

// ---------------------------------------------------------------------------
extern "C" void kernel_launch(void* const* d_in, const int* in_sizes, int n_in,
                              void* d_out, int out_size) {
    const float* X    = (const float*)d_in[0];  // [4, 8192, 1024]
    const float* W    = (const float*)d_in[1];  // [1024, 1024]
    const float* bias = (const float*)d_in[2];  // [1024]
    float* out = (float*)d_out;                 // [4, 8192, 1024]

    dim3 ggrid(DIM / BN, M_TOT / BM);   // (8, 256)
    gemm_gate_kernel<<<ggrid, 256>>>(X, W, bias);

    dim3 sgrid(DIM / 32, BATCH);        // (32, 4)
    scan_kernel<<<sgrid, 32>>>(out);
}

// round 2
// speedup vs baseline: 1.4540x; 1.4540x over previous
#include <cuda_runtime.h>
#include <cuda_bf16.h>
#include <cstdint>

// Problem constants: x [B=4, K=8192, D=1024], W [D,D], b [D]
#define BATCH 4
#define SEQ   8192
#define DIM   1024
#define M_TOT (BATCH * SEQ)   // 32768

// Chunked-scan constants
#define CH 128                // chunk length along K
#define NC (SEQ / CH)         // 64 chunks

// Scratch: interleaved {lam, u} per element, written by GEMM epilogue, read by scan.
__device__ float2 g_scratch[(size_t)M_TOT * DIM];
// Per-chunk aggregates {A = prod(lam), B = local scan end} and carry-in state.
__device__ float2 g_agg[(size_t)BATCH * NC * DIM];
__device__ float  g_carry[(size_t)BATCH * NC * DIM];

// ---------------------------------------------------------------------------
// GEMM + sigmoid gate epilogue (TF32 mma.sync)
//   z[m,n] = sum_d x[m,d] * W[n,d] + b[n]
//   lam = sigmoid(z); u = (1-lam)*x[m,n]; scratch[m,n] = {lam, u}
// Tile: BM=128, BN=128, BK=16, 256 threads (8 warps, 2x4), warp tile 64x32.
// ---------------------------------------------------------------------------
#define BM 128
#define BN 128
#define BK 16
#define PADK 20   // row pad: conflict-free frag LDS + 16B-aligned cp.async chunks
#define NKT (DIM / BK)   // 64

__device__ __forceinline__ uint32_t f2tf32(float f) {
    uint32_t r;
    asm volatile("cvt.rna.tf32.f32 %0, %1;" : "=r"(r) : "f"(f));
    return r;
}

__device__ __forceinline__ void cp_async16(uint32_t saddr, const void* gptr) {
    asm volatile("cp.async.cg.shared.global [%0], [%1], 16;" :: "r"(saddr), "l"(gptr));
}
__device__ __forceinline__ void cp_commit() {
    asm volatile("cp.async.commit_group;");
}
template <int N>
__device__ __forceinline__ void cp_wait() {
    asm volatile("cp.async.wait_group %0;" :: "n"(N));
}

__device__ __forceinline__ void mma_tf32(float& c0, float& c1, float& c2, float& c3,
                                         uint32_t a0, uint32_t a1, uint32_t a2, uint32_t a3,
                                         uint32_t b0, uint32_t b1) {
    asm volatile(
        "mma.sync.aligned.m16n8k8.row.col.f32.tf32.tf32.f32 "
        "{%0,%1,%2,%3},{%4,%5,%6,%7},{%8,%9},{%0,%1,%2,%3};"
        : "+f"(c0), "+f"(c1), "+f"(c2), "+f"(c3)
        : "r"(a0), "r"(a1), "r"(a2), "r"(a3), "r"(b0), "r"(b1));
}

__global__ __launch_bounds__(256, 2)
void gemm_gate_kernel(const float* __restrict__ X, const float* __restrict__ W,
                      const float* __restrict__ bias) {
    __shared__ __align__(16) float As[2][BM][PADK];
    __shared__ __align__(16) float Bs[2][BN][PADK];

    const int tid  = threadIdx.x;
    const int lane = tid & 31;
    const int wid  = tid >> 5;
    const int wm   = wid >> 2;   // 0..1  (M direction, 64 rows each)
    const int wn   = wid & 3;    // 0..3  (N direction, 32 cols each)
    const int m0   = blockIdx.y * BM;
    const int n0   = blockIdx.x * BN;

    // copy-index mapping: 512 16B-chunks per tile, 2 per thread
    const int r1 = tid >> 2,         s1 = tid & 3;          // chunk tid
    const int r2 = (tid + 256) >> 2, s2 = (tid + 256) & 3;  // chunk tid+256

    auto prefetch = [&](int kt, int st) {
        const int k0 = kt * BK;
        cp_async16((uint32_t)__cvta_generic_to_shared(&As[st][r1][s1 * 4]),
                   X + (size_t)(m0 + r1) * DIM + k0 + s1 * 4);
        cp_async16((uint32_t)__cvta_generic_to_shared(&As[st][r2][s2 * 4]),
                   X + (size_t)(m0 + r2) * DIM + k0 + s2 * 4);
        cp_async16((uint32_t)__cvta_generic_to_shared(&Bs[st][r1][s1 * 4]),
                   W + (size_t)(n0 + r1) * DIM + k0 + s1 * 4);
        cp_async16((uint32_t)__cvta_generic_to_shared(&Bs[st][r2][s2 * 4]),
                   W + (size_t)(n0 + r2) * DIM + k0 + s2 * 4);
    };

    float c[4][4][4];
    #pragma unroll
    for (int mi = 0; mi < 4; mi++)
        #pragma unroll
        for (int ni = 0; ni < 4; ni++)
            #pragma unroll
            for (int i = 0; i < 4; i++) c[mi][ni][i] = 0.0f;

    prefetch(0, 0);
    cp_commit();

    const int lq = lane >> 2;  // 0..7
    const int lr = lane & 3;   // 0..3

    for (int kt = 0; kt < NKT; kt++) {
        if (kt + 1 < NKT) prefetch(kt + 1, (kt + 1) & 1);
        cp_commit();
        cp_wait<1>();
        __syncthreads();

        const int st = kt & 1;
        #pragma unroll
        for (int ks = 0; ks < 2; ks++) {
            const int kk = ks * 8;
            uint32_t a[4][4], bf[4][2];
            #pragma unroll
            for (int mi = 0; mi < 4; mi++) {
                const int r = wm * 64 + mi * 16 + lq;
                a[mi][0] = f2tf32(As[st][r][kk + lr]);
                a[mi][1] = f2tf32(As[st][r + 8][kk + lr]);
                a[mi][2] = f2tf32(As[st][r][kk + lr + 4]);
                a[mi][3] = f2tf32(As[st][r + 8][kk + lr + 4]);
            }
            #pragma unroll
            for (int ni = 0; ni < 4; ni++) {
                const int cc = wn * 32 + ni * 8 + lq;
                bf[ni][0] = f2tf32(Bs[st][cc][kk + lr]);
                bf[ni][1] = f2tf32(Bs[st][cc][kk + lr + 4]);
            }
            #pragma unroll
            for (int mi = 0; mi < 4; mi++)
                #pragma unroll
                for (int ni = 0; ni < 4; ni++)
                    mma_tf32(c[mi][ni][0], c[mi][ni][1], c[mi][ni][2], c[mi][ni][3],
                             a[mi][0], a[mi][1], a[mi][2], a[mi][3],
                             bf[ni][0], bf[ni][1]);
        }
        __syncthreads();
    }

    // Epilogue: z -> lam -> {lam, (1-lam)*x}, 16B stores (two adjacent cols)
    #pragma unroll
    for (int ni = 0; ni < 4; ni++) {
        const int cb = n0 + wn * 32 + ni * 8 + 2 * lr;
        const float b0 = __ldg(&bias[cb]);
        const float b1 = __ldg(&bias[cb + 1]);
        #pragma unroll
        for (int mi = 0; mi < 4; mi++) {
            const int rb = m0 + wm * 64 + mi * 16 + lq;
            #pragma unroll
            for (int h = 0; h < 2; h++) {
                const int row = rb + h * 8;
                const float z0 = c[mi][ni][h * 2 + 0] + b0;
                const float z1 = c[mi][ni][h * 2 + 1] + b1;
                const float lam0 = 1.0f / (1.0f + __expf(-z0));
                const float lam1 = 1.0f / (1.0f + __expf(-z1));
                const float2 xv = *reinterpret_cast<const float2*>(
                    X + (size_t)row * DIM + cb);
                float4 outv;
                outv.x = lam0;
                outv.y = (1.0f - lam0) * xv.x;
                outv.z = lam1;
                outv.w = (1.0f - lam1) * xv.y;
                *reinterpret_cast<float4*>(&g_scratch[(size_t)row * DIM + cb]) = outv;
            }
        }
    }
}

// ---------------------------------------------------------------------------
// Chunked parallel scan. Affine maps compose associatively:
//   (a2,b2) o (a1,b1) = (a2*a1, a2*b1 + b2)
// Pass 1: per (b, chunk, d) aggregate A = prod(lam), B = local scan end.
// Pass 2: per (b, d) sequential scan over NC chunk aggregates -> carry-in.
// Pass 3: per (b, chunk, d) redo local recurrence seeded with carry, write out.
// ---------------------------------------------------------------------------
#define P_U 8   // prefetch depth inside a chunk

__global__ __launch_bounds__(256)
void scan_pass1() {
    const int d = blockIdx.x * 256 + threadIdx.x;  // 0..1023
    const int c = blockIdx.y;                       // chunk
    const int b = blockIdx.z;                       // batch
    const float2* __restrict__ p =
        g_scratch + ((size_t)(b * SEQ + c * CH) * DIM + d);

    float2 buf[2][P_U];
    #pragma unroll
    for (int i = 0; i < P_U; i++) buf[0][i] = p[(size_t)i * DIM];

    float A = 1.0f, s = 0.0f;
    int cur = 0;
    for (int k = 0; k < CH; k += P_U) {
        if (k + P_U < CH) {
            #pragma unroll
            for (int i = 0; i < P_U; i++)
                buf[cur ^ 1][i] = p[(size_t)(k + P_U + i) * DIM];
        }
        #pragma unroll
        for (int i = 0; i < P_U; i++) {
            const float lam = buf[cur][i].x;
            s = fmaf(lam, s, buf[cur][i].y);
            A *= lam;
        }
        cur ^= 1;
    }
    g_agg[((size_t)b * NC + c) * DIM + d] = make_float2(A, s);
}

__global__ __launch_bounds__(256)
void scan_pass2() {
    const int d = blockIdx.x * 256 + threadIdx.x;  // 0..1023
    const int b = blockIdx.y;
    float s = 0.0f;
    #pragma unroll 4
    for (int c = 0; c < NC; c++) {
        const size_t idx = ((size_t)b * NC + c) * DIM + d;
        const float2 ab = g_agg[idx];
        g_carry[idx] = s;
        s = fmaf(ab.x, s, ab.y);
    }
}

__global__ __launch_bounds__(256)
void scan_pass3(float* __restrict__ out) {
    const int d = blockIdx.x * 256 + threadIdx.x;
    const int c = blockIdx.y;
    const int b = blockIdx.z;
    const size_t base = (size_t)(b * SEQ + c * CH) * DIM + d;
    const float2* __restrict__ p = g_scratch + base;
    float* __restrict__ o = out + base;

    float2 buf[2][P_U];
    #pragma unroll
    for (int i = 0; i < P_U; i++) buf[0][i] = p[(size_t)i * DIM];

    float s = g_carry[((size_t)b * NC + c) * DIM + d];
    int cur = 0;
    for (int k = 0; k < CH; k += P_U) {
        if (k + P_U < CH) {
            #pragma unroll
            for (int i = 0; i < P_U; i++)
                buf[cur ^ 1][i] = p[(size_t)(k + P_U + i) * DIM];
        }
        #pragma unroll
        for (int i = 0; i < P_U; i++) {
            s = fmaf(buf[cur][i].x, s, buf[cur][i].y);
            o[(size_t)(k + i) * DIM] = s;
        }
        cur ^= 1;
    }
}

// ---------------------------------------------------------------------------
extern "C" void kernel_launch(void* const* d_in, const int* in_sizes, int n_in,
                              void* d_out, int out_size) {
    const float* X    = (const float*)d_in[0];  // [4, 8192, 1024]
    const float* W    = (const float*)d_in[1];  // [1024, 1024]
    const float* bias = (const float*)d_in[2];  // [1024]
    float* out = (float*)d_out;                 // [4, 8192, 1024]

    dim3 ggrid(DIM / BN, M_TOT / BM);   // (8, 256)
    gemm_gate_kernel<<<ggrid, 256>>>(X, W, bias);

    dim3 g1(DIM / 256, NC, BATCH);      // (4, 64, 4) = 1024 CTAs
    scan_pass1<<<g1, 256>>>();

    dim3 g2(DIM / 256, BATCH);          // (4, 4)
    scan_pass2<<<g2, 256>>>();

    scan_pass3<<<g1, 256>>>(out);
}

// round 6
// speedup vs baseline: 1.5220x; 1.0467x over previous
#include <cuda_runtime.h>
#include <cuda_bf16.h>
#include <cstdint>

// Problem constants: x [B=4, K=8192, D=1024], W [D,D], b [D]
#define BATCH 4
#define SEQ   8192
#define DIM   1024
#define M_TOT (BATCH * SEQ)   // 32768

// Chunked-scan constants
#define CH 128
#define NC (SEQ / CH)         // 64

__device__ float2 g_scratch[(size_t)M_TOT * DIM];
__device__ float2 g_agg[(size_t)BATCH * NC * DIM];
__device__ float  g_carry[(size_t)BATCH * NC * DIM];

// ---------------------------------------------------------------------------
// GEMM + sigmoid gate epilogue (TF32 mma.sync + ldmatrix fragments)
//   z[m,n] = sum_d x[m,d] * W[n,d] + b[n]
//   lam = sigmoid(z); u = (1-lam)*x[m,n]; scratch[m,n] = {lam, u}
// Tile: BM=128, BN=128, BK=16, 256 threads (8 warps, 2x4), warp tile 64x32.
// Fragments loaded via ldmatrix.m8n8.x4.b16 (tf32 8x4 row == b16 8x8 row).
// Raw fp32 bits fed to tf32 MMA (HW truncates mantissa; no cvt instructions).
// ---------------------------------------------------------------------------
#define BM 128
#define BN 128
#define BK 16
#define PADK 20   // row pad: 80B stride -> conflict-free ldmatrix phases
#define NKT (DIM / BK)   // 64

__device__ __forceinline__ void cp_async16(uint32_t saddr, const void* gptr) {
    asm volatile("cp.async.cg.shared.global [%0], [%1], 16;" :: "r"(saddr), "l"(gptr));
}
__device__ __forceinline__ void cp_commit() {
    asm volatile("cp.async.commit_group;");
}
template <int N>
__device__ __forceinline__ void cp_wait() {
    asm volatile("cp.async.wait_group %0;" :: "n"(N));
}

__device__ __forceinline__ void ldsm_x4(uint32_t& r0, uint32_t& r1,
                                        uint32_t& r2, uint32_t& r3, uint32_t addr) {
    asm volatile("ldmatrix.sync.aligned.m8n8.x4.shared.b16 {%0,%1,%2,%3}, [%4];"
                 : "=r"(r0), "=r"(r1), "=r"(r2), "=r"(r3) : "r"(addr));
}

__device__ __forceinline__ void mma_tf32(float& c0, float& c1, float& c2, float& c3,
                                         uint32_t a0, uint32_t a1, uint32_t a2, uint32_t a3,
                                         uint32_t b0, uint32_t b1) {
    asm volatile(
        "mma.sync.aligned.m16n8k8.row.col.f32.tf32.tf32.f32 "
        "{%0,%1,%2,%3},{%4,%5,%6,%7},{%8,%9},{%0,%1,%2,%3};"
        : "+f"(c0), "+f"(c1), "+f"(c2), "+f"(c3)
        : "r"(a0), "r"(a1), "r"(a2), "r"(a3), "r"(b0), "r"(b1));
}

__global__ __launch_bounds__(256, 2)
void gemm_gate_kernel(const float* __restrict__ X, const float* __restrict__ W,
                      const float* __restrict__ bias) {
    __shared__ __align__(16) float As[2][BM][PADK];
    __shared__ __align__(16) float Bs[2][BN][PADK];

    const int tid  = threadIdx.x;
    const int lane = tid & 31;
    const int wid  = tid >> 5;
    const int wm   = wid >> 2;   // 0..1  (M direction, 64 rows each)
    const int wn   = wid & 3;    // 0..3  (N direction, 32 cols each)
    const int m0   = blockIdx.y * BM;
    const int n0   = blockIdx.x * BN;

    // copy-index mapping: 512 16B-chunks per tile, 2 per thread
    const int r1 = tid >> 2,         s1 = tid & 3;          // chunk tid
    const int r2 = (tid + 256) >> 2, s2 = (tid + 256) & 3;  // chunk tid+256

    auto prefetch = [&](int kt, int st) {
        const int k0 = kt * BK;
        cp_async16((uint32_t)__cvta_generic_to_shared(&As[st][r1][s1 * 4]),
                   X + (size_t)(m0 + r1) * DIM + k0 + s1 * 4);
        cp_async16((uint32_t)__cvta_generic_to_shared(&As[st][r2][s2 * 4]),
                   X + (size_t)(m0 + r2) * DIM + k0 + s2 * 4);
        cp_async16((uint32_t)__cvta_generic_to_shared(&Bs[st][r1][s1 * 4]),
                   W + (size_t)(n0 + r1) * DIM + k0 + s1 * 4);
        cp_async16((uint32_t)__cvta_generic_to_shared(&Bs[st][r2][s2 * 4]),
                   W + (size_t)(n0 + r2) * DIM + k0 + s2 * 4);
    };

    float c[4][4][4];
    #pragma unroll
    for (int mi = 0; mi < 4; mi++)
        #pragma unroll
        for (int ni = 0; ni < 4; ni++)
            #pragma unroll
            for (int i = 0; i < 4; i++) c[mi][ni][i] = 0.0f;

    prefetch(0, 0);
    cp_commit();

    // ldmatrix per-lane source rows/cols (within a warp):
    //  A matrices 0..3 = a0..a3 of one m16 tile:
    //   lane groups: 0-7 rows base+0..7 col kk | 8-15 rows base+8..15 col kk
    //                16-23 rows base+0..7 col kk+4 | 24-31 rows base+8..15 col kk+4
    const int a_row_l = (lane & 15);            // + wm*64 + mi*16
    const int a_col_l = (lane >> 4) * 4;        // + kk
    //  B matrices 0..3 = b(2p)0, b(2p)1, b(2p+1)0, b(2p+1)1:
    const int b_row_l = ((lane >> 4) & 1) * 8 + (lane & 7);  // + wn*32 + p*16
    const int b_col_l = ((lane >> 3) & 1) * 4;               // + kk

    const int lq = lane >> 2;  // 0..7 (fragment row within 8)
    const int lr = lane & 3;   // 0..3

    for (int kt = 0; kt < NKT; kt++) {
        if (kt + 1 < NKT) prefetch(kt + 1, (kt + 1) & 1);
        cp_commit();
        cp_wait<1>();
        __syncthreads();

        const int st = kt & 1;
        #pragma unroll
        for (int ks = 0; ks < 2; ks++) {
            const int kk = ks * 8;
            uint32_t a[4][4], bf[2][4];
            #pragma unroll
            for (int mi = 0; mi < 4; mi++) {
                const uint32_t addr = (uint32_t)__cvta_generic_to_shared(
                    &As[st][wm * 64 + mi * 16 + a_row_l][kk + a_col_l]);
                ldsm_x4(a[mi][0], a[mi][1], a[mi][2], a[mi][3], addr);
            }
            #pragma unroll
            for (int p = 0; p < 2; p++) {
                const uint32_t addr = (uint32_t)__cvta_generic_to_shared(
                    &Bs[st][wn * 32 + p * 16 + b_row_l][kk + b_col_l]);
                ldsm_x4(bf[p][0], bf[p][1], bf[p][2], bf[p][3], addr);
            }
            #pragma unroll
            for (int mi = 0; mi < 4; mi++)
                #pragma unroll
                for (int ni = 0; ni < 4; ni++)
                    mma_tf32(c[mi][ni][0], c[mi][ni][1], c[mi][ni][2], c[mi][ni][3],
                             a[mi][0], a[mi][1], a[mi][2], a[mi][3],
                             bf[ni >> 1][(ni & 1) * 2], bf[ni >> 1][(ni & 1) * 2 + 1]);
        }
        __syncthreads();
    }

    // Epilogue: z -> lam -> {lam, (1-lam)*x}, 16B stores (two adjacent cols)
    #pragma unroll
    for (int ni = 0; ni < 4; ni++) {
        const int cb = n0 + wn * 32 + ni * 8 + 2 * lr;
        const float b0 = __ldg(&bias[cb]);
        const float b1 = __ldg(&bias[cb + 1]);
        #pragma unroll
        for (int mi = 0; mi < 4; mi++) {
            const int rb = m0 + wm * 64 + mi * 16 + lq;
            #pragma unroll
            for (int h = 0; h < 2; h++) {
                const int row = rb + h * 8;
                const float z0 = c[mi][ni][h * 2 + 0] + b0;
                const float z1 = c[mi][ni][h * 2 + 1] + b1;
                const float lam0 = 1.0f / (1.0f + __expf(-z0));
                const float lam1 = 1.0f / (1.0f + __expf(-z1));
                const float2 xv = *reinterpret_cast<const float2*>(
                    X + (size_t)row * DIM + cb);
                float4 outv;
                outv.x = lam0;
                outv.y = (1.0f - lam0) * xv.x;
                outv.z = lam1;
                outv.w = (1.0f - lam1) * xv.y;
                *reinterpret_cast<float4*>(&g_scratch[(size_t)row * DIM + cb]) = outv;
            }
        }
    }
}

// ---------------------------------------------------------------------------
// Chunked parallel scan (2 chains per thread, float4 traffic)
// ---------------------------------------------------------------------------
#define P_U 8

__global__ __launch_bounds__(128)
void scan_pass1() {
    const int t = blockIdx.x * 128 + threadIdx.x;   // 0..511
    const int d0 = 2 * t;
    const int c = blockIdx.y, b = blockIdx.z;
    const float4* __restrict__ p =
        (const float4*)(g_scratch + ((size_t)(b * SEQ + c * CH) * DIM + d0));
    const int STRIDE = DIM / 2;

    float4 buf[2][P_U];
    #pragma unroll
    for (int i = 0; i < P_U; i++) buf[0][i] = p[i * STRIDE];

    float A0 = 1.0f, s0 = 0.0f, A1 = 1.0f, s1 = 0.0f;
    int cur = 0;
    for (int k = 0; k < CH; k += P_U) {
        const float4* pn = p + (k + P_U) * STRIDE;
        if (k + P_U < CH) {
            #pragma unroll
            for (int i = 0; i < P_U; i++) buf[cur ^ 1][i] = pn[i * STRIDE];
        }
        #pragma unroll
        for (int i = 0; i < P_U; i++) {
            const float4 v = buf[cur][i];
            s0 = fmaf(v.x, s0, v.y); A0 *= v.x;
            s1 = fmaf(v.z, s1, v.w); A1 *= v.z;
        }
        cur ^= 1;
    }
    float4* ag = (float4*)(g_agg + ((size_t)(b * NC + c) * DIM + d0));
    float4 o; o.x = A0; o.y = s0; o.z = A1; o.w = s1;
    *ag = o;
}

__global__ __launch_bounds__(128)
void scan_pass2() {
    const int t = blockIdx.x * 128 + threadIdx.x;   // 0..511
    const int d0 = 2 * t;
    const int b = blockIdx.y;
    float s0 = 0.0f, s1 = 0.0f;
    #pragma unroll 4
    for (int c = 0; c < NC; c++) {
        const size_t idx = (size_t)(b * NC + c) * DIM + d0;
        const float4 ab = *(const float4*)(g_agg + idx);
        float2 cr; cr.x = s0; cr.y = s1;
        *(float2*)(g_carry + idx) = cr;
        s0 = fmaf(ab.x, s0, ab.y);
        s1 = fmaf(ab.z, s1, ab.w);
    }
}

__global__ __launch_bounds__(128)
void scan_pass3(float* __restrict__ out) {
    const int t = blockIdx.x * 128 + threadIdx.x;
    const int d0 = 2 * t;
    const int c = blockIdx.y, b = blockIdx.z;
    const size_t base = (size_t)(b * SEQ + c * CH) * DIM + d0;
    const float4* __restrict__ p = (const float4*)(g_scratch + base);
    float* __restrict__ o = out + base;
    const int STRIDE = DIM / 2;

    float4 buf[2][P_U];
    #pragma unroll
    for (int i = 0; i < P_U; i++) buf[0][i] = p[i * STRIDE];

    const float2 cr = *(const float2*)(g_carry + ((size_t)(b * NC + c) * DIM + d0));
    float s0 = cr.x, s1 = cr.y;
    int cur = 0;
    for (int k = 0; k < CH; k += P_U) {
        const float4* pn = p + (k + P_U) * STRIDE;
        if (k + P_U < CH) {
            #pragma unroll
            for (int i = 0; i < P_U; i++) buf[cur ^ 1][i] = pn[i * STRIDE];
        }
        #pragma unroll
        for (int i = 0; i < P_U; i++) {
            const float4 v = buf[cur][i];
            s0 = fmaf(v.x, s0, v.y);
            s1 = fmaf(v.z, s1, v.w);
            float2 ov; ov.x = s0; ov.y = s1;
            *(float2*)(o + (size_t)(k + i) * DIM) = ov;
        }
        cur ^= 1;
    }
}

// ---------------------------------------------------------------------------
extern "C" void kernel_launch(void* const* d_in, const int* in_sizes, int n_in,
                              void* d_out, int out_size) {
    const float* X    = (const float*)d_in[0];  // [4, 8192, 1024]
    const float* W    = (const float*)d_in[1];  // [1024, 1024]
    const float* bias = (const float*)d_in[2];  // [1024]
    float* out = (float*)d_out;                 // [4, 8192, 1024]

    dim3 ggrid(DIM / BN, M_TOT / BM);   // (8, 256)
    gemm_gate_kernel<<<ggrid, 256>>>(X, W, bias);

    dim3 g1(DIM / 256, NC, BATCH);      // (4, 64, 4)
    scan_pass1<<<g1, 128>>>();
    dim3 g2(DIM / 256, BATCH);          // (4, 4)
    scan_pass2<<<g2, 128>>>();
    scan_pass3<<<g1, 128>>>(out);
}

// round 10
// speedup vs baseline: 1.9777x; 1.2995x over previous
#include <cuda_runtime.h>
#include <cuda_fp16.h>
#include <cstdint>

// Problem constants: x [B=4, K=8192, D=1024], W [D,D], b [D]
#define BATCH 4
#define SEQ   8192
#define DIM   1024
#define M_TOT (BATCH * SEQ)   // 32768

// Chunked-scan constants
#define CH 128
#define NC (SEQ / CH)         // 64

__device__ float2 g_scratch[(size_t)M_TOT * DIM];
__device__ float2 g_agg[(size_t)BATCH * NC * DIM];
__device__ float  g_carry[(size_t)BATCH * NC * DIM];
__device__ __half g_Xh[(size_t)M_TOT * DIM];
__device__ __half g_Wh[(size_t)DIM * DIM];

// ---------------------------------------------------------------------------
// fp32 -> fp16 conversion pre-passes
// ---------------------------------------------------------------------------
__global__ __launch_bounds__(256)
void convert_kernel(const float* __restrict__ src, __half* __restrict__ dst,
                    int n4) {   // n4 = element count / 4
    const int stride = gridDim.x * 256;
    for (int i = blockIdx.x * 256 + threadIdx.x; i < n4; i += stride) {
        const float4 v = *(const float4*)(src + (size_t)i * 4);
        __half2 h0 = __floats2half2_rn(v.x, v.y);
        __half2 h1 = __floats2half2_rn(v.z, v.w);
        uint2 o;
        o.x = *(uint32_t*)&h0;
        o.y = *(uint32_t*)&h1;
        *(uint2*)(dst + (size_t)i * 4) = o;
    }
}

// ---------------------------------------------------------------------------
// GEMM + sigmoid gate epilogue (FP16 mma.sync m16n8k16 + ldmatrix)
//   z[m,n] = sum_d x[m,d] * W[n,d] + b[n]   (fp16 inputs, fp32 accumulate)
//   lam = sigmoid(z); u = (1-lam)*x[m,n]; scratch[m,n] = {lam, u}
// Tile: BM=128, BN=128, BK=32, 256 threads (8 warps, 2x4), warp tile 64x32.
// ---------------------------------------------------------------------------
#define BM 128
#define BN 128
#define BK 32
#define PADH 40   // halves per row: 80B stride -> conflict-free ldmatrix phases
#define NKT (DIM / BK)   // 32

__device__ __forceinline__ void cp_async16(uint32_t saddr, const void* gptr) {
    asm volatile("cp.async.cg.shared.global [%0], [%1], 16;" :: "r"(saddr), "l"(gptr));
}
__device__ __forceinline__ void cp_commit() {
    asm volatile("cp.async.commit_group;");
}
template <int N>
__device__ __forceinline__ void cp_wait() {
    asm volatile("cp.async.wait_group %0;" :: "n"(N));
}

__device__ __forceinline__ void ldsm_x4(uint32_t& r0, uint32_t& r1,
                                        uint32_t& r2, uint32_t& r3, uint32_t addr) {
    asm volatile("ldmatrix.sync.aligned.m8n8.x4.shared.b16 {%0,%1,%2,%3}, [%4];"
                 : "=r"(r0), "=r"(r1), "=r"(r2), "=r"(r3) : "r"(addr));
}

__device__ __forceinline__ void mma_f16(float& c0, float& c1, float& c2, float& c3,
                                        uint32_t a0, uint32_t a1, uint32_t a2, uint32_t a3,
                                        uint32_t b0, uint32_t b1) {
    asm volatile(
        "mma.sync.aligned.m16n8k16.row.col.f32.f16.f16.f32 "
        "{%0,%1,%2,%3},{%4,%5,%6,%7},{%8,%9},{%0,%1,%2,%3};"
        : "+f"(c0), "+f"(c1), "+f"(c2), "+f"(c3)
        : "r"(a0), "r"(a1), "r"(a2), "r"(a3), "r"(b0), "r"(b1));
}

__global__ __launch_bounds__(256, 2)
void gemm_gate_kernel(const float* __restrict__ X, const float* __restrict__ bias) {
    __shared__ __align__(16) __half As[2][BM][PADH];
    __shared__ __align__(16) __half Bs[2][BN][PADH];

    const int tid  = threadIdx.x;
    const int lane = tid & 31;
    const int wid  = tid >> 5;
    const int wm   = wid >> 2;   // 0..1  (M direction, 64 rows each)
    const int wn   = wid & 3;    // 0..3  (N direction, 32 cols each)
    const int m0   = blockIdx.y * BM;
    const int n0   = blockIdx.x * BN;

    // copy mapping: 128 rows x 4 chunks (16B = 8 halves) = 512 chunks, 2/thread
    const int r1 = tid >> 2,         s1 = tid & 3;
    const int r2 = (tid + 256) >> 2, s2 = (tid + 256) & 3;

    auto prefetch = [&](int kt, int st) {
        const int k0 = kt * BK;
        cp_async16((uint32_t)__cvta_generic_to_shared(&As[st][r1][s1 * 8]),
                   g_Xh + (size_t)(m0 + r1) * DIM + k0 + s1 * 8);
        cp_async16((uint32_t)__cvta_generic_to_shared(&As[st][r2][s2 * 8]),
                   g_Xh + (size_t)(m0 + r2) * DIM + k0 + s2 * 8);
        cp_async16((uint32_t)__cvta_generic_to_shared(&Bs[st][r1][s1 * 8]),
                   g_Wh + (size_t)(n0 + r1) * DIM + k0 + s1 * 8);
        cp_async16((uint32_t)__cvta_generic_to_shared(&Bs[st][r2][s2 * 8]),
                   g_Wh + (size_t)(n0 + r2) * DIM + k0 + s2 * 8);
    };

    float c[4][4][4];
    #pragma unroll
    for (int mi = 0; mi < 4; mi++)
        #pragma unroll
        for (int ni = 0; ni < 4; ni++)
            #pragma unroll
            for (int i = 0; i < 4; i++) c[mi][ni][i] = 0.0f;

    prefetch(0, 0);
    cp_commit();

    // A fragment (m16n8k16): ldmatrix.x4 lane->address mapping:
    //  lanes 0-7: rows 0-7 @ k0 | 8-15: rows 8-15 @ k0
    //  lanes 16-23: rows 0-7 @ k8 | 24-31: rows 8-15 @ k8
    const int a_row_l = (lane & 15);            // + wm*64 + mi*16
    const int a_col_l = (lane >> 4) * 8;        // + kk
    // B fragment: per ldmatrix.x4 (covers 2 n8-tiles x both k-halves):
    //  lanes 0-7: n-rows 0-7 @ k0 | 8-15: n-rows 0-7 @ k8
    //  lanes 16-23: n-rows 8-15 @ k0 | 24-31: n-rows 8-15 @ k8
    const int b_row_l = ((lane >> 4) & 1) * 8 + (lane & 7);  // + wn*32 + p*16
    const int b_col_l = ((lane >> 3) & 1) * 8;               // + kk

    const int lq = lane >> 2;  // 0..7
    const int lr = lane & 3;   // 0..3

    for (int kt = 0; kt < NKT; kt++) {
        if (kt + 1 < NKT) prefetch(kt + 1, (kt + 1) & 1);
        cp_commit();
        cp_wait<1>();
        __syncthreads();

        const int st = kt & 1;
        #pragma unroll
        for (int ks = 0; ks < 2; ks++) {
            const int kk = ks * 16;
            uint32_t a[4][4], bf[2][4];
            #pragma unroll
            for (int mi = 0; mi < 4; mi++) {
                const uint32_t addr = (uint32_t)__cvta_generic_to_shared(
                    &As[st][wm * 64 + mi * 16 + a_row_l][kk + a_col_l]);
                ldsm_x4(a[mi][0], a[mi][1], a[mi][2], a[mi][3], addr);
            }
            #pragma unroll
            for (int p = 0; p < 2; p++) {
                const uint32_t addr = (uint32_t)__cvta_generic_to_shared(
                    &Bs[st][wn * 32 + p * 16 + b_row_l][kk + b_col_l]);
                ldsm_x4(bf[p][0], bf[p][1], bf[p][2], bf[p][3], addr);
            }
            #pragma unroll
            for (int mi = 0; mi < 4; mi++)
                #pragma unroll
                for (int ni = 0; ni < 4; ni++)
                    mma_f16(c[mi][ni][0], c[mi][ni][1], c[mi][ni][2], c[mi][ni][3],
                            a[mi][0], a[mi][1], a[mi][2], a[mi][3],
                            bf[ni >> 1][(ni & 1) * 2], bf[ni >> 1][(ni & 1) * 2 + 1]);
        }
        __syncthreads();
    }

    // Epilogue: z -> lam -> {lam, (1-lam)*x}, 16B stores (two adjacent cols)
    #pragma unroll
    for (int ni = 0; ni < 4; ni++) {
        const int cb = n0 + wn * 32 + ni * 8 + 2 * lr;
        const float b0 = __ldg(&bias[cb]);
        const float b1 = __ldg(&bias[cb + 1]);
        #pragma unroll
        for (int mi = 0; mi < 4; mi++) {
            const int rb = m0 + wm * 64 + mi * 16 + lq;
            #pragma unroll
            for (int h = 0; h < 2; h++) {
                const int row = rb + h * 8;
                const float z0 = c[mi][ni][h * 2 + 0] + b0;
                const float z1 = c[mi][ni][h * 2 + 1] + b1;
                const float lam0 = 1.0f / (1.0f + __expf(-z0));
                const float lam1 = 1.0f / (1.0f + __expf(-z1));
                const float2 xv = *reinterpret_cast<const float2*>(
                    X + (size_t)row * DIM + cb);
                float4 outv;
                outv.x = lam0;
                outv.y = (1.0f - lam0) * xv.x;
                outv.z = lam1;
                outv.w = (1.0f - lam1) * xv.y;
                *reinterpret_cast<float4*>(&g_scratch[(size_t)row * DIM + cb]) = outv;
            }
        }
    }
}

// ---------------------------------------------------------------------------
// Chunked parallel scan (2 chains per thread, float4 traffic)
// ---------------------------------------------------------------------------
#define P_U 8

__global__ __launch_bounds__(128)
void scan_pass1() {
    const int t = blockIdx.x * 128 + threadIdx.x;   // 0..511
    const int d0 = 2 * t;
    const int c = blockIdx.y, b = blockIdx.z;
    const float4* __restrict__ p =
        (const float4*)(g_scratch + ((size_t)(b * SEQ + c * CH) * DIM + d0));
    const int STRIDE = DIM / 2;

    float4 buf[2][P_U];
    #pragma unroll
    for (int i = 0; i < P_U; i++) buf[0][i] = p[i * STRIDE];

    float A0 = 1.0f, s0 = 0.0f, A1 = 1.0f, s1 = 0.0f;
    int cur = 0;
    for (int k = 0; k < CH; k += P_U) {
        const float4* pn = p + (k + P_U) * STRIDE;
        if (k + P_U < CH) {
            #pragma unroll
            for (int i = 0; i < P_U; i++) buf[cur ^ 1][i] = pn[i * STRIDE];
        }
        #pragma unroll
        for (int i = 0; i < P_U; i++) {
            const float4 v = buf[cur][i];
            s0 = fmaf(v.x, s0, v.y); A0 *= v.x;
            s1 = fmaf(v.z, s1, v.w); A1 *= v.z;
        }
        cur ^= 1;
    }
    float4* ag = (float4*)(g_agg + ((size_t)(b * NC + c) * DIM + d0));
    float4 o; o.x = A0; o.y = s0; o.z = A1; o.w = s1;
    *ag = o;
}

__global__ __launch_bounds__(128)
void scan_pass2() {
    const int t = blockIdx.x * 128 + threadIdx.x;   // 0..511
    const int d0 = 2 * t;
    const int b = blockIdx.y;
    float s0 = 0.0f, s1 = 0.0f;
    #pragma unroll 4
    for (int c = 0; c < NC; c++) {
        const size_t idx = (size_t)(b * NC + c) * DIM + d0;
        const float4 ab = *(const float4*)(g_agg + idx);
        float2 cr; cr.x = s0; cr.y = s1;
        *(float2*)(g_carry + idx) = cr;
        s0 = fmaf(ab.x, s0, ab.y);
        s1 = fmaf(ab.z, s1, ab.w);
    }
}

__global__ __launch_bounds__(128)
void scan_pass3(float* __restrict__ out) {
    const int t = blockIdx.x * 128 + threadIdx.x;
    const int d0 = 2 * t;
    const int c = blockIdx.y, b = blockIdx.z;
    const size_t base = (size_t)(b * SEQ + c * CH) * DIM + d0;
    const float4* __restrict__ p = (const float4*)(g_scratch + base);
    float* __restrict__ o = out + base;
    const int STRIDE = DIM / 2;

    float4 buf[2][P_U];
    #pragma unroll
    for (int i = 0; i < P_U; i++) buf[0][i] = p[i * STRIDE];

    const float2 cr = *(const float2*)(g_carry + ((size_t)(b * NC + c) * DIM + d0));
    float s0 = cr.x, s1 = cr.y;
    int cur = 0;
    for (int k = 0; k < CH; k += P_U) {
        const float4* pn = p + (k + P_U) * STRIDE;
        if (k + P_U < CH) {
            #pragma unroll
            for (int i = 0; i < P_U; i++) buf[cur ^ 1][i] = pn[i * STRIDE];
        }
        #pragma unroll
        for (int i = 0; i < P_U; i++) {
            const float4 v = buf[cur][i];
            s0 = fmaf(v.x, s0, v.y);
            s1 = fmaf(v.z, s1, v.w);
            float2 ov; ov.x = s0; ov.y = s1;
            *(float2*)(o + (size_t)(k + i) * DIM) = ov;
        }
        cur ^= 1;
    }
}

// ---------------------------------------------------------------------------
extern "C" void kernel_launch(void* const* d_in, const int* in_sizes, int n_in,
                              void* d_out, int out_size) {
    const float* X    = (const float*)d_in[0];  // [4, 8192, 1024]
    const float* W    = (const float*)d_in[1];  // [1024, 1024]
    const float* bias = (const float*)d_in[2];  // [1024]
    float* out = (float*)d_out;                 // [4, 8192, 1024]

    __half* Xh = nullptr;
    __half* Wh = nullptr;
    cudaGetSymbolAddress((void**)&Xh, g_Xh);
    cudaGetSymbolAddress((void**)&Wh, g_Wh);

    convert_kernel<<<2048, 256>>>(X, Xh, (M_TOT * DIM) / 4);
    convert_kernel<<<256, 256>>>(W, Wh, (DIM * DIM) / 4);

    dim3 ggrid(DIM / BN, M_TOT / BM);   // (8, 256)
    gemm_gate_kernel<<<ggrid, 256>>>(X, bias);

    dim3 g1(DIM / 256, NC, BATCH);      // (4, 64, 4)
    scan_pass1<<<g1, 128>>>();
    dim3 g2(DIM / 256, BATCH);          // (4, 4)
    scan_pass2<<<g2, 128>>>();
    scan_pass3<<<g1, 128>>>(out);
}

// round 12
// speedup vs baseline: 2.3812x; 1.2040x over previous
#include <cuda_runtime.h>
#include <cuda_fp16.h>
#include <cstdint>

// Problem constants: x [B=4, K=8192, D=1024], W [D,D], b [D]
#define BATCH 4
#define SEQ   8192
#define DIM   1024
#define M_TOT (BATCH * SEQ)   // 32768

// Chunked-scan constants
#define CH 128
#define NC (SEQ / CH)         // 64

// Scratch: packed {lam, u} as half2 per (m,d) element (4B), 128MB total.
__device__ __half2 g_scratch_h[(size_t)M_TOT * DIM];
__device__ float2  g_agg[(size_t)BATCH * NC * DIM];
__device__ float   g_carry[(size_t)BATCH * NC * DIM];
__device__ __half  g_Xh[(size_t)M_TOT * DIM];
__device__ __half  g_Wh[(size_t)DIM * DIM];

// ---------------------------------------------------------------------------
// fp32 -> fp16 conversion pre-passes
// ---------------------------------------------------------------------------
__global__ __launch_bounds__(256)
void convert_kernel(const float* __restrict__ src, __half* __restrict__ dst,
                    int n4) {   // n4 = element count / 4
    const int stride = gridDim.x * 256;
    for (int i = blockIdx.x * 256 + threadIdx.x; i < n4; i += stride) {
        const float4 v = *(const float4*)(src + (size_t)i * 4);
        __half2 h0 = __floats2half2_rn(v.x, v.y);
        __half2 h1 = __floats2half2_rn(v.z, v.w);
        uint2 o;
        o.x = *(uint32_t*)&h0;
        o.y = *(uint32_t*)&h1;
        *(uint2*)(dst + (size_t)i * 4) = o;
    }
}

// ---------------------------------------------------------------------------
// GEMM + sigmoid gate epilogue (FP16 mma.sync m16n8k16 + ldmatrix)
// Tile: BM=128, BN=128, BK=32, 256 threads (8 warps, 2x4), warp tile 64x32.
// ---------------------------------------------------------------------------
#define BM 128
#define BN 128
#define BK 32
#define PADH 40   // halves per row: 80B stride -> conflict-free ldmatrix phases
#define NKT (DIM / BK)   // 32

__device__ __forceinline__ void cp_async16(uint32_t saddr, const void* gptr) {
    asm volatile("cp.async.cg.shared.global [%0], [%1], 16;" :: "r"(saddr), "l"(gptr));
}
__device__ __forceinline__ void cp_commit() {
    asm volatile("cp.async.commit_group;");
}
template <int N>
__device__ __forceinline__ void cp_wait() {
    asm volatile("cp.async.wait_group %0;" :: "n"(N));
}

__device__ __forceinline__ void ldsm_x4(uint32_t& r0, uint32_t& r1,
                                        uint32_t& r2, uint32_t& r3, uint32_t addr) {
    asm volatile("ldmatrix.sync.aligned.m8n8.x4.shared.b16 {%0,%1,%2,%3}, [%4];"
                 : "=r"(r0), "=r"(r1), "=r"(r2), "=r"(r3) : "r"(addr));
}

__device__ __forceinline__ void mma_f16(float& c0, float& c1, float& c2, float& c3,
                                        uint32_t a0, uint32_t a1, uint32_t a2, uint32_t a3,
                                        uint32_t b0, uint32_t b1) {
    asm volatile(
        "mma.sync.aligned.m16n8k16.row.col.f32.f16.f16.f32 "
        "{%0,%1,%2,%3},{%4,%5,%6,%7},{%8,%9},{%0,%1,%2,%3};"
        : "+f"(c0), "+f"(c1), "+f"(c2), "+f"(c3)
        : "r"(a0), "r"(a1), "r"(a2), "r"(a3), "r"(b0), "r"(b1));
}

__global__ __launch_bounds__(256, 2)
void gemm_gate_kernel(const float* __restrict__ bias) {
    __shared__ __align__(16) __half As[2][BM][PADH];
    __shared__ __align__(16) __half Bs[2][BN][PADH];

    const int tid  = threadIdx.x;
    const int lane = tid & 31;
    const int wid  = tid >> 5;
    const int wm   = wid >> 2;   // 0..1  (M direction, 64 rows each)
    const int wn   = wid & 3;    // 0..3  (N direction, 32 cols each)
    const int m0   = blockIdx.y * BM;
    const int n0   = blockIdx.x * BN;

    // copy mapping: 128 rows x 4 chunks (16B = 8 halves) = 512 chunks, 2/thread
    const int r1 = tid >> 2,         s1 = tid & 3;
    const int r2 = (tid + 256) >> 2, s2 = (tid + 256) & 3;

    auto prefetch = [&](int kt, int st) {
        const int k0 = kt * BK;
        cp_async16((uint32_t)__cvta_generic_to_shared(&As[st][r1][s1 * 8]),
                   g_Xh + (size_t)(m0 + r1) * DIM + k0 + s1 * 8);
        cp_async16((uint32_t)__cvta_generic_to_shared(&As[st][r2][s2 * 8]),
                   g_Xh + (size_t)(m0 + r2) * DIM + k0 + s2 * 8);
        cp_async16((uint32_t)__cvta_generic_to_shared(&Bs[st][r1][s1 * 8]),
                   g_Wh + (size_t)(n0 + r1) * DIM + k0 + s1 * 8);
        cp_async16((uint32_t)__cvta_generic_to_shared(&Bs[st][r2][s2 * 8]),
                   g_Wh + (size_t)(n0 + r2) * DIM + k0 + s2 * 8);
    };

    float c[4][4][4];
    #pragma unroll
    for (int mi = 0; mi < 4; mi++)
        #pragma unroll
        for (int ni = 0; ni < 4; ni++)
            #pragma unroll
            for (int i = 0; i < 4; i++) c[mi][ni][i] = 0.0f;

    prefetch(0, 0);
    cp_commit();

    // A fragment (m16n8k16) ldmatrix.x4 lane mapping
    const int a_row_l = (lane & 15);            // + wm*64 + mi*16
    const int a_col_l = (lane >> 4) * 8;        // + kk
    // B fragment (2 n8-tiles x both k-halves per x4)
    const int b_row_l = ((lane >> 4) & 1) * 8 + (lane & 7);  // + wn*32 + p*16
    const int b_col_l = ((lane >> 3) & 1) * 8;               // + kk

    const int lq = lane >> 2;  // 0..7
    const int lr = lane & 3;   // 0..3

    for (int kt = 0; kt < NKT; kt++) {
        if (kt + 1 < NKT) prefetch(kt + 1, (kt + 1) & 1);
        cp_commit();
        cp_wait<1>();
        __syncthreads();

        const int st = kt & 1;
        #pragma unroll
        for (int ks = 0; ks < 2; ks++) {
            const int kk = ks * 16;
            uint32_t a[4][4], bf[2][4];
            #pragma unroll
            for (int mi = 0; mi < 4; mi++) {
                const uint32_t addr = (uint32_t)__cvta_generic_to_shared(
                    &As[st][wm * 64 + mi * 16 + a_row_l][kk + a_col_l]);
                ldsm_x4(a[mi][0], a[mi][1], a[mi][2], a[mi][3], addr);
            }
            #pragma unroll
            for (int p = 0; p < 2; p++) {
                const uint32_t addr = (uint32_t)__cvta_generic_to_shared(
                    &Bs[st][wn * 32 + p * 16 + b_row_l][kk + b_col_l]);
                ldsm_x4(bf[p][0], bf[p][1], bf[p][2], bf[p][3], addr);
            }
            #pragma unroll
            for (int mi = 0; mi < 4; mi++)
                #pragma unroll
                for (int ni = 0; ni < 4; ni++)
                    mma_f16(c[mi][ni][0], c[mi][ni][1], c[mi][ni][2], c[mi][ni][3],
                            a[mi][0], a[mi][1], a[mi][2], a[mi][3],
                            bf[ni >> 1][(ni & 1) * 2], bf[ni >> 1][(ni & 1) * 2 + 1]);
        }
        __syncthreads();
    }

    // Epilogue: z -> lam -> packed half2 {lam, (1-lam)*x}; x read from fp16 Xh.
    #pragma unroll
    for (int ni = 0; ni < 4; ni++) {
        const int cb = n0 + wn * 32 + ni * 8 + 2 * lr;
        const float b0 = __ldg(&bias[cb]);
        const float b1 = __ldg(&bias[cb + 1]);
        #pragma unroll
        for (int mi = 0; mi < 4; mi++) {
            const int rb = m0 + wm * 64 + mi * 16 + lq;
            #pragma unroll
            for (int h = 0; h < 2; h++) {
                const int row = rb + h * 8;
                const size_t idx = (size_t)row * DIM + cb;
                const float z0 = c[mi][ni][h * 2 + 0] + b0;
                const float z1 = c[mi][ni][h * 2 + 1] + b1;
                const float lam0 = 1.0f / (1.0f + __expf(-z0));
                const float lam1 = 1.0f / (1.0f + __expf(-z1));
                const __half2 xh = *reinterpret_cast<const __half2*>(&g_Xh[idx]);
                const float2 xf = __half22float2(xh);
                __half2 o0 = __floats2half2_rn(lam0, (1.0f - lam0) * xf.x);
                __half2 o1 = __floats2half2_rn(lam1, (1.0f - lam1) * xf.y);
                uint2 pk;
                pk.x = *(uint32_t*)&o0;
                pk.y = *(uint32_t*)&o1;
                *reinterpret_cast<uint2*>(&g_scratch_h[idx]) = pk;
            }
        }
    }
}

// ---------------------------------------------------------------------------
// Chunked parallel scan (4 chains per thread, uint4 = 4x half2 traffic)
// ---------------------------------------------------------------------------
#define P_U 8

__device__ __forceinline__ float2 upk(uint32_t w) {
    __half2 h = *reinterpret_cast<__half2*>(&w);
    return __half22float2(h);   // {lam, u}
}

__global__ __launch_bounds__(128)
void scan_pass1() {
    const int t = blockIdx.x * 128 + threadIdx.x;   // 0..255
    const int d0 = 4 * t;
    const int c = blockIdx.y, b = blockIdx.z;
    const uint4* __restrict__ p =
        (const uint4*)(g_scratch_h + ((size_t)(b * SEQ + c * CH) * DIM + d0));
    const int STRIDE = DIM / 4;

    uint4 buf[2][P_U];
    #pragma unroll
    for (int i = 0; i < P_U; i++) buf[0][i] = p[i * STRIDE];

    float A0 = 1.f, A1 = 1.f, A2 = 1.f, A3 = 1.f;
    float s0 = 0.f, s1 = 0.f, s2 = 0.f, s3 = 0.f;
    int cur = 0;
    for (int k = 0; k < CH; k += P_U) {
        const uint4* pn = p + (k + P_U) * STRIDE;
        if (k + P_U < CH) {
            #pragma unroll
            for (int i = 0; i < P_U; i++) buf[cur ^ 1][i] = pn[i * STRIDE];
        }
        #pragma unroll
        for (int i = 0; i < P_U; i++) {
            const uint4 v = buf[cur][i];
            float2 e;
            e = upk(v.x); s0 = fmaf(e.x, s0, e.y); A0 *= e.x;
            e = upk(v.y); s1 = fmaf(e.x, s1, e.y); A1 *= e.x;
            e = upk(v.z); s2 = fmaf(e.x, s2, e.y); A2 *= e.x;
            e = upk(v.w); s3 = fmaf(e.x, s3, e.y); A3 *= e.x;
        }
        cur ^= 1;
    }
    float2* ag = g_agg + ((size_t)(b * NC + c) * DIM + d0);
    float4 o0, o1;
    o0.x = A0; o0.y = s0; o0.z = A1; o0.w = s1;
    o1.x = A2; o1.y = s2; o1.z = A3; o1.w = s3;
    *(float4*)(ag)     = o0;
    *(float4*)(ag + 2) = o1;
}

__global__ __launch_bounds__(256)
void scan_pass2() {
    const int t = threadIdx.x;   // 0..255
    const int d0 = 4 * t;
    const int b = blockIdx.y;
    float s0 = 0.f, s1 = 0.f, s2 = 0.f, s3 = 0.f;
    #pragma unroll 4
    for (int c = 0; c < NC; c++) {
        const size_t idx = (size_t)(b * NC + c) * DIM + d0;
        const float4 ab0 = *(const float4*)(g_agg + idx);
        const float4 ab1 = *(const float4*)(g_agg + idx + 2);
        float4 cr; cr.x = s0; cr.y = s1; cr.z = s2; cr.w = s3;
        *(float4*)(g_carry + idx) = cr;
        s0 = fmaf(ab0.x, s0, ab0.y);
        s1 = fmaf(ab0.z, s1, ab0.w);
        s2 = fmaf(ab1.x, s2, ab1.y);
        s3 = fmaf(ab1.z, s3, ab1.w);
    }
}

__global__ __launch_bounds__(128)
void scan_pass3(float* __restrict__ out) {
    const int t = blockIdx.x * 128 + threadIdx.x;
    const int d0 = 4 * t;
    const int c = blockIdx.y, b = blockIdx.z;
    const size_t base = (size_t)(b * SEQ + c * CH) * DIM + d0;
    const uint4* __restrict__ p = (const uint4*)(g_scratch_h + base);
    float* __restrict__ o = out + base;
    const int STRIDE = DIM / 4;

    uint4 buf[2][P_U];
    #pragma unroll
    for (int i = 0; i < P_U; i++) buf[0][i] = p[i * STRIDE];

    const float4 cr = *(const float4*)(g_carry + ((size_t)(b * NC + c) * DIM + d0));
    float s0 = cr.x, s1 = cr.y, s2 = cr.z, s3 = cr.w;
    int cur = 0;
    for (int k = 0; k < CH; k += P_U) {
        const uint4* pn = p + (k + P_U) * STRIDE;
        if (k + P_U < CH) {
            #pragma unroll
            for (int i = 0; i < P_U; i++) buf[cur ^ 1][i] = pn[i * STRIDE];
        }
        #pragma unroll
        for (int i = 0; i < P_U; i++) {
            const uint4 v = buf[cur][i];
            float2 e;
            e = upk(v.x); s0 = fmaf(e.x, s0, e.y);
            e = upk(v.y); s1 = fmaf(e.x, s1, e.y);
            e = upk(v.z); s2 = fmaf(e.x, s2, e.y);
            e = upk(v.w); s3 = fmaf(e.x, s3, e.y);
            float4 ov; ov.x = s0; ov.y = s1; ov.z = s2; ov.w = s3;
            *(float4*)(o + (size_t)(k + i) * DIM) = ov;
        }
        cur ^= 1;
    }
}

// ---------------------------------------------------------------------------
extern "C" void kernel_launch(void* const* d_in, const int* in_sizes, int n_in,
                              void* d_out, int out_size) {
    const float* X    = (const float*)d_in[0];  // [4, 8192, 1024]
    const float* W    = (const float*)d_in[1];  // [1024, 1024]
    const float* bias = (const float*)d_in[2];  // [1024]
    float* out = (float*)d_out;                 // [4, 8192, 1024]

    __half* Xh = nullptr;
    __half* Wh = nullptr;
    cudaGetSymbolAddress((void**)&Xh, g_Xh);
    cudaGetSymbolAddress((void**)&Wh, g_Wh);

    convert_kernel<<<2048, 256>>>(X, Xh, (M_TOT * DIM) / 4);
    convert_kernel<<<256, 256>>>(W, Wh, (DIM * DIM) / 4);

    dim3 ggrid(DIM / BN, M_TOT / BM);   // (8, 256)
    gemm_gate_kernel<<<ggrid, 256>>>(bias);

    dim3 g1(DIM / (4 * 128), NC, BATCH);   // (2, 64, 4)
    scan_pass1<<<g1, 128>>>();
    dim3 g2(1, BATCH);
    scan_pass2<<<g2, 256>>>();
    scan_pass3<<<g1, 128>>>(out);
}

// round 15
// speedup vs baseline: 2.4670x; 1.0360x over previous
#include <cuda_runtime.h>
#include <cuda_fp16.h>
#include <cstdint>

// Problem constants: x [B=4, K=8192, D=1024], W [D,D], b [D]
#define BATCH 4
#define SEQ   8192
#define DIM   1024
#define M_TOT (BATCH * SEQ)   // 32768

// Chunked-scan constants (chunk = 64 steps; GEMM tile of 128 rows = 2 chunks)
#define CH 64
#define NC (SEQ / CH)         // 128

__device__ __half2 g_scratch_h[(size_t)M_TOT * DIM];
__device__ float2  g_agg[(size_t)BATCH * NC * DIM];
__device__ float   g_carry[(size_t)BATCH * NC * DIM];
__device__ __half  g_Xh[(size_t)M_TOT * DIM];
__device__ __half  g_Wh[(size_t)DIM * DIM];

// ---------------------------------------------------------------------------
// fp32 -> fp16 conversion pre-passes
// ---------------------------------------------------------------------------
__global__ __launch_bounds__(256)
void convert_kernel(const float* __restrict__ src, __half* __restrict__ dst,
                    int n4) {
    const int stride = gridDim.x * 256;
    for (int i = blockIdx.x * 256 + threadIdx.x; i < n4; i += stride) {
        const float4 v = *(const float4*)(src + (size_t)i * 4);
        __half2 h0 = __floats2half2_rn(v.x, v.y);
        __half2 h1 = __floats2half2_rn(v.z, v.w);
        uint2 o;
        o.x = *(uint32_t*)&h0;
        o.y = *(uint32_t*)&h1;
        *(uint2*)(dst + (size_t)i * 4) = o;
    }
}

// ---------------------------------------------------------------------------
// GEMM + sigmoid gate + FUSED chunk aggregation (pass1)
// Tile: BM=128, BN=128, BK=32, 256 threads (8 warps, 2x4), warp tile 64x32.
// Dynamic SMEM: As/Bs double-buffered tiles (40KB) reused as 64KB half2 tile
// for the fused column scan after the MMA main loop.
// ---------------------------------------------------------------------------
#define BM 128
#define BN 128
#define BK 32
#define PADH 40   // halves per row: 80B stride -> conflict-free ldmatrix phases
#define NKT (DIM / BK)   // 32
#define SMEM_BYTES 65536

__device__ __forceinline__ void cp_async16(uint32_t saddr, const void* gptr) {
    asm volatile("cp.async.cg.shared.global [%0], [%1], 16;" :: "r"(saddr), "l"(gptr));
}
__device__ __forceinline__ void cp_commit() {
    asm volatile("cp.async.commit_group;");
}
template <int N>
__device__ __forceinline__ void cp_wait() {
    asm volatile("cp.async.wait_group %0;" :: "n"(N));
}

__device__ __forceinline__ void ldsm_x4(uint32_t& r0, uint32_t& r1,
                                        uint32_t& r2, uint32_t& r3, uint32_t addr) {
    asm volatile("ldmatrix.sync.aligned.m8n8.x4.shared.b16 {%0,%1,%2,%3}, [%4];"
                 : "=r"(r0), "=r"(r1), "=r"(r2), "=r"(r3) : "r"(addr));
}

__device__ __forceinline__ void mma_f16(float& c0, float& c1, float& c2, float& c3,
                                        uint32_t a0, uint32_t a1, uint32_t a2, uint32_t a3,
                                        uint32_t b0, uint32_t b1) {
    asm volatile(
        "mma.sync.aligned.m16n8k16.row.col.f32.f16.f16.f32 "
        "{%0,%1,%2,%3},{%4,%5,%6,%7},{%8,%9},{%0,%1,%2,%3};"
        : "+f"(c0), "+f"(c1), "+f"(c2), "+f"(c3)
        : "r"(a0), "r"(a1), "r"(a2), "r"(a3), "r"(b0), "r"(b1));
}

__global__ __launch_bounds__(256, 2)
void gemm_gate_kernel(const float* __restrict__ bias) {
    extern __shared__ __align__(16) char dsm[];
    __half* As = (__half*)dsm;                       // [2][BM][PADH]
    __half* Bs = As + 2 * BM * PADH;                 // [2][BN][PADH]
    __half2* S = (__half2*)dsm;                      // [BM][BN] (reused)

    const int tid  = threadIdx.x;
    const int lane = tid & 31;
    const int wid  = tid >> 5;
    const int wm   = wid >> 2;
    const int wn   = wid & 3;
    const int m0   = blockIdx.y * BM;
    const int n0   = blockIdx.x * BN;

    const int r1 = tid >> 2,         s1 = tid & 3;
    const int r2 = (tid + 256) >> 2, s2 = (tid + 256) & 3;

    auto prefetch = [&](int kt, int st) {
        const int k0 = kt * BK;
        cp_async16((uint32_t)__cvta_generic_to_shared(&As[(st * BM + r1) * PADH + s1 * 8]),
                   g_Xh + (size_t)(m0 + r1) * DIM + k0 + s1 * 8);
        cp_async16((uint32_t)__cvta_generic_to_shared(&As[(st * BM + r2) * PADH + s2 * 8]),
                   g_Xh + (size_t)(m0 + r2) * DIM + k0 + s2 * 8);
        cp_async16((uint32_t)__cvta_generic_to_shared(&Bs[(st * BN + r1) * PADH + s1 * 8]),
                   g_Wh + (size_t)(n0 + r1) * DIM + k0 + s1 * 8);
        cp_async16((uint32_t)__cvta_generic_to_shared(&Bs[(st * BN + r2) * PADH + s2 * 8]),
                   g_Wh + (size_t)(n0 + r2) * DIM + k0 + s2 * 8);
    };

    float c[4][4][4];
    #pragma unroll
    for (int mi = 0; mi < 4; mi++)
        #pragma unroll
        for (int ni = 0; ni < 4; ni++)
            #pragma unroll
            for (int i = 0; i < 4; i++) c[mi][ni][i] = 0.0f;

    prefetch(0, 0);
    cp_commit();

    const int a_row_l = (lane & 15);
    const int a_col_l = (lane >> 4) * 8;
    const int b_row_l = ((lane >> 4) & 1) * 8 + (lane & 7);
    const int b_col_l = ((lane >> 3) & 1) * 8;

    const int lq = lane >> 2;
    const int lr = lane & 3;

    for (int kt = 0; kt < NKT; kt++) {
        if (kt + 1 < NKT) prefetch(kt + 1, (kt + 1) & 1);
        cp_commit();
        cp_wait<1>();
        __syncthreads();

        const int st = kt & 1;
        #pragma unroll
        for (int ks = 0; ks < 2; ks++) {
            const int kk = ks * 16;
            uint32_t a[4][4], bf[2][4];
            #pragma unroll
            for (int mi = 0; mi < 4; mi++) {
                const uint32_t addr = (uint32_t)__cvta_generic_to_shared(
                    &As[(st * BM + wm * 64 + mi * 16 + a_row_l) * PADH + kk + a_col_l]);
                ldsm_x4(a[mi][0], a[mi][1], a[mi][2], a[mi][3], addr);
            }
            #pragma unroll
            for (int p = 0; p < 2; p++) {
                const uint32_t addr = (uint32_t)__cvta_generic_to_shared(
                    &Bs[(st * BN + wn * 32 + p * 16 + b_row_l) * PADH + kk + b_col_l]);
                ldsm_x4(bf[p][0], bf[p][1], bf[p][2], bf[p][3], addr);
            }
            #pragma unroll
            for (int mi = 0; mi < 4; mi++)
                #pragma unroll
                for (int ni = 0; ni < 4; ni++)
                    mma_f16(c[mi][ni][0], c[mi][ni][1], c[mi][ni][2], c[mi][ni][3],
                            a[mi][0], a[mi][1], a[mi][2], a[mi][3],
                            bf[ni >> 1][(ni & 1) * 2], bf[ni >> 1][(ni & 1) * 2 + 1]);
        }
        __syncthreads();
    }
    // All As/Bs reads complete (loop-ending __syncthreads) — safe to reuse as S.

    // Phase A: z -> lam -> packed half2 {lam, u}; write gmem scratch + SMEM tile.
    #pragma unroll
    for (int ni = 0; ni < 4; ni++) {
        const int cb_l = wn * 32 + ni * 8 + 2 * lr;
        const float b0 = __ldg(&bias[n0 + cb_l]);
        const float b1 = __ldg(&bias[n0 + cb_l + 1]);
        #pragma unroll
        for (int mi = 0; mi < 4; mi++) {
            #pragma unroll
            for (int h = 0; h < 2; h++) {
                const int row_l = wm * 64 + mi * 16 + h * 8 + lq;
                const size_t idx = (size_t)(m0 + row_l) * DIM + n0 + cb_l;
                const float z0 = c[mi][ni][h * 2 + 0] + b0;
                const float z1 = c[mi][ni][h * 2 + 1] + b1;
                const float lam0 = 1.0f / (1.0f + __expf(-z0));
                const float lam1 = 1.0f / (1.0f + __expf(-z1));
                const __half2 xh = *reinterpret_cast<const __half2*>(&g_Xh[idx]);
                const float2 xf = __half22float2(xh);
                __half2 o0 = __floats2half2_rn(lam0, (1.0f - lam0) * xf.x);
                __half2 o1 = __floats2half2_rn(lam1, (1.0f - lam1) * xf.y);
                uint2 pk;
                pk.x = *(uint32_t*)&o0;
                pk.y = *(uint32_t*)&o1;
                *reinterpret_cast<uint2*>(&g_scratch_h[idx]) = pk;
                *reinterpret_cast<uint2*>(&S[row_l * BN + cb_l]) = pk;
            }
        }
    }
    __syncthreads();

    // Phase B: fused pass1 — column scans over 64-row chunks.
    // 256 threads: col = tid&127, half = tid>>7 (rows [half*64, half*64+64)).
    {
        const int col  = tid & 127;
        const int half = tid >> 7;
        const int b    = m0 / SEQ;
        const int cidx = ((m0 % SEQ) >> 6) + half;   // global chunk index
        float A = 1.0f, s = 0.0f;
        #pragma unroll 8
        for (int r = 0; r < 64; r++) {
            const float2 e = __half22float2(S[(half * 64 + r) * BN + col]);
            s = fmaf(e.x, s, e.y);
            A *= e.x;
        }
        g_agg[((size_t)(b * NC + cidx)) * DIM + n0 + col] = make_float2(A, s);
    }
}

// ---------------------------------------------------------------------------
// pass2: sequential scan over NC=128 chunk aggregates per chain.
// ---------------------------------------------------------------------------
__global__ __launch_bounds__(256)
void scan_pass2() {
    const int t = threadIdx.x;   // 0..255
    const int d0 = 4 * t;
    const int b = blockIdx.y;
    float s0 = 0.f, s1 = 0.f, s2 = 0.f, s3 = 0.f;
    #pragma unroll 4
    for (int c = 0; c < NC; c++) {
        const size_t idx = (size_t)(b * NC + c) * DIM + d0;
        const float4 ab0 = *(const float4*)(g_agg + idx);
        const float4 ab1 = *(const float4*)(g_agg + idx + 2);
        float4 cr; cr.x = s0; cr.y = s1; cr.z = s2; cr.w = s3;
        *(float4*)(g_carry + idx) = cr;
        s0 = fmaf(ab0.x, s0, ab0.y);
        s1 = fmaf(ab0.z, s1, ab0.w);
        s2 = fmaf(ab1.x, s2, ab1.y);
        s3 = fmaf(ab1.z, s3, ab1.w);
    }
}

// ---------------------------------------------------------------------------
// pass3: local recurrence seeded with carry (4 chains/thread, uint4 loads).
// ---------------------------------------------------------------------------
#define P_U 8

__device__ __forceinline__ float2 upk(uint32_t w) {
    __half2 h = *reinterpret_cast<__half2*>(&w);
    return __half22float2(h);
}

__global__ __launch_bounds__(128)
void scan_pass3(float* __restrict__ out) {
    const int t = blockIdx.x * 128 + threadIdx.x;
    const int d0 = 4 * t;
    const int c = blockIdx.y, b = blockIdx.z;
    const size_t base = (size_t)(b * SEQ + c * CH) * DIM + d0;
    const uint4* __restrict__ p = (const uint4*)(g_scratch_h + base);
    float* __restrict__ o = out + base;
    const int STRIDE = DIM / 4;

    uint4 buf[2][P_U];
    #pragma unroll
    for (int i = 0; i < P_U; i++) buf[0][i] = p[i * STRIDE];

    const float4 cr = *(const float4*)(g_carry + ((size_t)(b * NC + c) * DIM + d0));
    float s0 = cr.x, s1 = cr.y, s2 = cr.z, s3 = cr.w;
    int cur = 0;
    for (int k = 0; k < CH; k += P_U) {
        const uint4* pn = p + (k + P_U) * STRIDE;
        if (k + P_U < CH) {
            #pragma unroll
            for (int i = 0; i < P_U; i++) buf[cur ^ 1][i] = pn[i * STRIDE];
        }
        #pragma unroll
        for (int i = 0; i < P_U; i++) {
            const uint4 v = buf[cur][i];
            float2 e;
            e = upk(v.x); s0 = fmaf(e.x, s0, e.y);
            e = upk(v.y); s1 = fmaf(e.x, s1, e.y);
            e = upk(v.z); s2 = fmaf(e.x, s2, e.y);
            e = upk(v.w); s3 = fmaf(e.x, s3, e.y);
            float4 ov; ov.x = s0; ov.y = s1; ov.z = s2; ov.w = s3;
            *(float4*)(o + (size_t)(k + i) * DIM) = ov;
        }
        cur ^= 1;
    }
}

// ---------------------------------------------------------------------------
extern "C" void kernel_launch(void* const* d_in, const int* in_sizes, int n_in,
                              void* d_out, int out_size) {
    const float* X    = (const float*)d_in[0];
    const float* W    = (const float*)d_in[1];
    const float* bias = (const float*)d_in[2];
    float* out = (float*)d_out;

    __half* Xh = nullptr;
    __half* Wh = nullptr;
    cudaGetSymbolAddress((void**)&Xh, g_Xh);
    cudaGetSymbolAddress((void**)&Wh, g_Wh);

    convert_kernel<<<2048, 256>>>(X, Xh, (M_TOT * DIM) / 4);
    convert_kernel<<<256, 256>>>(W, Wh, (DIM * DIM) / 4);

    // Idempotent, non-stream API: call unconditionally (no static guards).
    cudaFuncSetAttribute(gemm_gate_kernel,
                         cudaFuncAttributeMaxDynamicSharedMemorySize, SMEM_BYTES);

    dim3 ggrid(DIM / BN, M_TOT / BM);   // (8, 256)
    gemm_gate_kernel<<<ggrid, 256, SMEM_BYTES>>>(bias);

    dim3 g2(1, BATCH);
    scan_pass2<<<g2, 256>>>();

    dim3 g3(DIM / (4 * 128), NC, BATCH);   // (2, 128, 4)
    scan_pass3<<<g3, 128>>>(out);
}